// round 2
// baseline (speedup 1.0000x reference)
#include <cuda_runtime.h>

#define HH 1024
#define WW 1024
#define BATCH 16
#define NIMG (HH*WW)
#define NTEN (BATCH*NIMG)

// Tile: 128 cols x 64 rows per block. Block = (32,4) = 128 threads.
// Each thread: 4 columns (float4) x 16 output rows, register-rolling pipeline.
#define TX 128
#define TY 64
#define RPT 16                     // rows per thread
#define SROWS (TY + 4)             // 68 smem rows (halo 2 each side)
#define SCOLS 132                  // 128 + 2*2 halo; smem[s] = x[x0 + s - 2]

__device__ float g_buf0[2*NTEN];
__device__ float g_buf1[2*NTEN];
__device__ double g_acc[4];

__device__ __forceinline__ float PINF() { return __int_as_float(0x7f800000); }
__device__ __forceinline__ float NINF() { return __int_as_float(0xff800000); }

__global__ void zero_acc_kernel() {
    if (threadIdx.x < 4) g_acc[threadIdx.x] = 0.0;
}

// Fill smem tile: smem[r][s] = x[y0-2+r][x0-2+s], +inf outside image.
__device__ __forceinline__ void fill_tile(float (*sx)[SCOLS],
                                          const float* __restrict__ src,
                                          int x0, int y0, int tid)
{
    #pragma unroll 4
    for (int r = 0; r < SROWS; r++) {
        int gy = y0 - 2 + r;
        bool vy = (gy >= 0) && (gy < HH);
        const float* row = src + gy * WW;
        for (int s = tid; s < SCOLS; s += 128) {
            int gx = x0 - 2 + s;
            float v = PINF();
            if (vy && gx >= 0 && gx < WW) v = __ldg(row + gx);
            sx[r][s] = v;
        }
    }
}

// Register-rolling skeleton step for one thread's 4-col x 16-row patch.
// EMIT(k, yy, o4) is invoked for k>=4 with o4 = float4 of outputs at row yy-2.
#define SKEL_PIPELINE(EMIT_BODY)                                               \
    const int lane = threadIdx.x;                                              \
    const int ty   = threadIdx.y;                                              \
    const int Xl   = 4 * lane;            /* col offset in tile */             \
    const int gX   = x0 + Xl;             /* global col of output 0 */         \
    bool cok[6];                                                               \
    _Pragma("unroll")                                                          \
    for (int j = 0; j < 6; j++) {                                              \
        int gc = gX - 1 + j;                                                   \
        cok[j] = (gc >= 0) && (gc < WW);                                       \
    }                                                                          \
    const int yStart = y0 + RPT * ty;                                          \
    float h0[6], h1[6], h2[6], g0[4], g1[4], g2[4];                            \
    float vmc[4], xc_a[4], xc_b[4];                                            \
    _Pragma("unroll")                                                          \
    for (int j = 0; j < 6; j++) { h0[j] = 0.f; h1[j] = 0.f; }                  \
    _Pragma("unroll")                                                          \
    for (int j = 0; j < 4; j++) { g0[j] = 0.f; g1[j] = 0.f;                    \
                                  vmc[j] = 0.f; xc_a[j] = 0.f; xc_b[j] = 0.f; }\
    _Pragma("unroll")                                                          \
    for (int k = 0; k < RPT + 4; k++) {                                        \
        const int yy = yStart - 2 + k;                                         \
        const int r  = yy - y0 + 2;                                            \
        const float* rowp = &sx[r][Xl];                                        \
        float4 A = *(const float4*)(rowp);                                     \
        float4 B = *(const float4*)(rowp + 4);                                 \
        float x8[8] = {A.x, A.y, A.z, A.w, B.x, B.y, B.z, B.w};                \
        _Pragma("unroll")                                                      \
        for (int j = 0; j < 6; j++)                                            \
            h2[j] = fminf(fminf(x8[j], x8[j+1]), x8[j+2]);                     \
        float vm[6];                                                           \
        _Pragma("unroll")                                                      \
        for (int j = 0; j < 6; j++)                                            \
            vm[j] = fminf(fminf(h0[j], h1[j]), h2[j]);                         \
        const bool rok = ((yy - 1) >= 0) && ((yy - 1) < HH);                   \
        float vmM[6];                                                          \
        _Pragma("unroll")                                                      \
        for (int j = 0; j < 6; j++)                                            \
            vmM[j] = (rok && cok[j]) ? vm[j] : NINF();                         \
        _Pragma("unroll")                                                      \
        for (int j = 0; j < 4; j++)                                            \
            g2[j] = fmaxf(fmaxf(vmM[j], vmM[j+1]), vmM[j+2]);                  \
        if (k >= 4) {                                                          \
            float4 o4;                                                         \
            float* op = &o4.x;                                                 \
            _Pragma("unroll")                                                  \
            for (int j = 0; j < 4; j++) {                                      \
                float mp      = fmaxf(fmaxf(g0[j], g1[j]), g2[j]);             \
                float contour = fmaxf(mp - vmc[j], 0.0f);                      \
                op[j]         = fmaxf(xc_a[j] - contour, 0.0f);                \
            }                                                                  \
            EMIT_BODY                                                          \
        }                                                                      \
        _Pragma("unroll")                                                      \
        for (int j = 0; j < 6; j++) { h0[j] = h1[j]; h1[j] = h2[j]; }          \
        _Pragma("unroll")                                                      \
        for (int j = 0; j < 4; j++) { g0[j] = g1[j]; g1[j] = g2[j]; }          \
        _Pragma("unroll")                                                      \
        for (int j = 0; j < 4; j++) { vmc[j]  = vm[j+1]; }                     \
        _Pragma("unroll")                                                      \
        for (int j = 0; j < 4; j++) { xc_a[j] = xc_b[j]; xc_b[j] = x8[j+2]; }  \
    }

__global__ __launch_bounds__(128, 4)
void skel_step_kernel(const float* __restrict__ src0, const float* __restrict__ src1,
                      float* __restrict__ dst)
{
    __shared__ float sx[SROWS][SCOLS];

    const int t = blockIdx.z / BATCH;
    const int b = blockIdx.z % BATCH;
    const float* src = (t == 0 ? src0 : src1) + b * NIMG;
    float* out = dst + t * NTEN + b * NIMG;

    const int x0 = blockIdx.x * TX;
    const int y0 = blockIdx.y * TY;
    const int tid = threadIdx.y * 32 + threadIdx.x;

    fill_tile(sx, src, x0, y0, tid);
    __syncthreads();

    SKEL_PIPELINE({
        *(float4*)(out + (yy - 2) * WW + gX) = o4;
    })
}

__global__ __launch_bounds__(128, 4)
void skel_final_kernel(const float* __restrict__ src0, const float* __restrict__ src1,
                       const float* __restrict__ other0, const float* __restrict__ other1)
{
    __shared__ float sx[SROWS][SCOLS];
    __shared__ float wprod[4], wsum[4];

    const int t = blockIdx.z / BATCH;
    const int b = blockIdx.z % BATCH;
    const float* src   = (t == 0 ? src0   : src1)   + b * NIMG;
    const float* other = (t == 0 ? other0 : other1) + b * NIMG;

    const int x0 = blockIdx.x * TX;
    const int y0 = blockIdx.y * TY;
    const int tid = threadIdx.y * 32 + threadIdx.x;

    fill_tile(sx, src, x0, y0, tid);
    __syncthreads();

    float s_prod = 0.0f, s_sum = 0.0f;
    SKEL_PIPELINE({
        const float4 ov = *(const float4*)(other + (yy - 2) * WW + gX);
        s_prod += o4.x * ov.x + o4.y * ov.y + o4.z * ov.z + o4.w * ov.w;
        s_sum  += o4.x + o4.y + o4.z + o4.w;
    })

    #pragma unroll
    for (int off = 16; off; off >>= 1) {
        s_prod += __shfl_down_sync(0xffffffffu, s_prod, off);
        s_sum  += __shfl_down_sync(0xffffffffu, s_sum,  off);
    }
    if (threadIdx.x == 0) { wprod[threadIdx.y] = s_prod; wsum[threadIdx.y] = s_sum; }
    __syncthreads();
    if (tid == 0) {
        double p = 0.0, s = 0.0;
        #pragma unroll
        for (int i = 0; i < 4; i++) { p += (double)wprod[i]; s += (double)wsum[i]; }
        atomicAdd(&g_acc[t*2 + 0], p);
        atomicAdd(&g_acc[t*2 + 1], s);
    }
}

__global__ void finish_kernel(float* __restrict__ out)
{
    double iflat = (g_acc[0] + 1.0) / (g_acc[1] + 1.0);
    double tflat = (g_acc[2] + 1.0) / (g_acc[3] + 1.0);
    double loss  = 1.0 - 2.0 * iflat * tflat / (iflat + tflat);
    out[0] = (float)loss;
}

extern "C" void kernel_launch(void* const* d_in, const int* in_sizes, int n_in,
                              void* d_out, int out_size)
{
    const float* pred = (const float*)d_in[0];
    const float* gt   = (const float*)d_in[1];
    float* out = (float*)d_out;

    float *b0 = nullptr, *b1 = nullptr;
    cudaGetSymbolAddress((void**)&b0, g_buf0);
    cudaGetSymbolAddress((void**)&b1, g_buf1);

    dim3 grid(WW / TX, HH / TY, 2 * BATCH);   // (8, 16, 32)
    dim3 block(32, 4);

    zero_acc_kernel<<<1, 32>>>();

    // Iteration 0 reads the harness inputs.
    skel_step_kernel<<<grid, block>>>(pred, gt, b0);

    // Iterations 1..18 ping-pong scratch.
    float* cur = b0;
    float* nxt = b1;
    for (int i = 1; i < 19; i++) {
        skel_step_kernel<<<grid, block>>>(cur, cur + NTEN, nxt);
        float* tmp = cur; cur = nxt; nxt = tmp;
    }

    // Iteration 19 fused with the reductions.
    skel_final_kernel<<<grid, block>>>(cur, cur + NTEN, gt, pred);

    finish_kernel<<<1, 1>>>(out);
}

// round 3
// speedup vs baseline: 3.8577x; 3.8577x over previous
#include <cuda_runtime.h>

#define HH 1024
#define WW 1024
#define BATCH 16
#define NIMG (HH*WW)
#define NTEN (BATCH*NIMG)
#define RSWEEP 32                  // output rows per warp sweep
#define FULLM 0xffffffffu

__device__ float g_buf0[2*NTEN];
__device__ float g_buf1[2*NTEN];
__device__ double g_acc[4];

__device__ __forceinline__ float PINF() { return __int_as_float(0x7f800000); }
__device__ __forceinline__ float NINF() { return __int_as_float(0xff800000); }
__device__ __forceinline__ float min3(float a, float b, float c) { return fminf(a, fminf(b, c)); }
__device__ __forceinline__ float max3(float a, float b, float c) { return fmaxf(a, fmaxf(b, c)); }

__global__ void zero_acc_kernel() {
    if (threadIdx.x < 4) g_acc[threadIdx.x] = 0.0;
}

// Warp-local skeleton sweep. Each warp: 128 columns (4/thread) x RSWEEP rows.
// Separable 3x3 min-pool then 3x3 max-pool, horizontal taps via shuffles,
// vertical taps via rolling registers. EMIT_BODY sees (orow, o) with o the
// float4 of outputs for global row 'orow' at columns gX..gX+3.
#define SKEL_SWEEP(EMIT_BODY)                                                  \
    const int lane  = threadIdx.x & 31;                                        \
    const int warp  = threadIdx.x >> 5;                                        \
    const int c0    = warp * 128;                                              \
    const int gX    = c0 + 4 * lane;                                           \
    const int r0    = blockIdx.x * RSWEEP;                                     \
    const bool leftok  = (warp > 0);                                           \
    const bool rightok = (warp < 7);                                           \
    float hA[4], hB[4], gA[4], gB[4], mC[4];                                   \
    float4 xA, xB;                                                             \
    float hlA = PINF(), hlB = PINF(), hrA = PINF(), hrB = PINF();              \
    _Pragma("unroll")                                                          \
    for (int j = 0; j < 4; j++) { hA[j]=PINF(); hB[j]=PINF();                  \
                                  gA[j]=NINF(); gB[j]=NINF(); mC[j]=0.f; }     \
    xA = make_float4(0.f,0.f,0.f,0.f); xB = xA;                                \
    _Pragma("unroll 6")                                                        \
    for (int k = 0; k < RSWEEP + 4; k++) {                                     \
        const int rr = r0 - 2 + k;                                             \
        const bool rv = (rr >= 0) && (rr < HH);                                \
        float4 A;                                                              \
        if (rv) A = *(const float4*)(src + (size_t)rr * WW + gX);              \
        else    A = make_float4(PINF(), PINF(), PINF(), PINF());               \
        float xl1 = PINF(), xl2 = PINF(), xr0 = PINF(), xr1 = PINF();          \
        if (lane == 0 && leftok && rv) {                                       \
            float2 tt = *(const float2*)(src + (size_t)rr * WW + c0 - 2);      \
            xl2 = tt.x; xl1 = tt.y;                                            \
        }                                                                      \
        if (lane == 31 && rightok && rv) {                                     \
            float2 tt = *(const float2*)(src + (size_t)rr * WW + c0 + 128);    \
            xr0 = tt.x; xr1 = tt.y;                                            \
        }                                                                      \
        float xm1 = __shfl_up_sync(FULLM, A.w, 1);                             \
        if (lane == 0) xm1 = xl1;                                              \
        float xp4 = __shfl_down_sync(FULLM, A.x, 1);                           \
        if (lane == 31) xp4 = xr0;                                             \
        float hC[4];                                                           \
        hC[0] = min3(xm1, A.x, A.y);                                           \
        hC[1] = min3(A.x, A.y, A.z);                                           \
        hC[2] = min3(A.y, A.z, A.w);                                           \
        hC[3] = min3(A.z, A.w, xp4);                                           \
        float hlC = min3(xl2, xl1, A.x);                                       \
        float hrC = min3(A.w, xr0, xr1);                                       \
        float m[4];                                                            \
        _Pragma("unroll")                                                      \
        for (int j = 0; j < 4; j++) m[j] = min3(hA[j], hB[j], hC[j]);          \
        float ml = min3(hlA, hlB, hlC);                                        \
        float mr = min3(hrA, hrB, hrC);                                        \
        const bool rvC = ((rr - 1) >= 0) && ((rr - 1) < HH);                   \
        float mM[4];                                                           \
        _Pragma("unroll")                                                      \
        for (int j = 0; j < 4; j++) mM[j] = rvC ? m[j] : NINF();               \
        float mlM = (leftok  && rvC) ? ml : NINF();                            \
        float mrM = (rightok && rvC) ? mr : NINF();                            \
        float mm1 = __shfl_up_sync(FULLM, mM[3], 1);                           \
        if (lane == 0) mm1 = mlM;                                              \
        float mp4 = __shfl_down_sync(FULLM, mM[0], 1);                         \
        if (lane == 31) mp4 = mrM;                                             \
        float gC[4];                                                           \
        gC[0] = max3(mm1,   mM[0], mM[1]);                                     \
        gC[1] = max3(mM[0], mM[1], mM[2]);                                     \
        gC[2] = max3(mM[1], mM[2], mM[3]);                                     \
        gC[3] = max3(mM[2], mM[3], mp4);                                       \
        if (k >= 4) {                                                          \
            const int orow = rr - 2;                                           \
            float4 o;                                                          \
            o.x = fmaxf(xA.x - fmaxf(max3(gA[0], gB[0], gC[0]) - mC[0], 0.f), 0.f); \
            o.y = fmaxf(xA.y - fmaxf(max3(gA[1], gB[1], gC[1]) - mC[1], 0.f), 0.f); \
            o.z = fmaxf(xA.z - fmaxf(max3(gA[2], gB[2], gC[2]) - mC[2], 0.f), 0.f); \
            o.w = fmaxf(xA.w - fmaxf(max3(gA[3], gB[3], gC[3]) - mC[3], 0.f), 0.f); \
            EMIT_BODY                                                          \
        }                                                                      \
        _Pragma("unroll")                                                      \
        for (int j = 0; j < 4; j++) {                                          \
            hA[j] = hB[j]; hB[j] = hC[j];                                      \
            gA[j] = gB[j]; gB[j] = gC[j];                                      \
            mC[j] = m[j];                                                      \
        }                                                                      \
        hlA = hlB; hlB = hlC; hrA = hrB; hrB = hrC;                            \
        xA = xB; xB = A;                                                       \
    }

__global__ __launch_bounds__(256)
void skel_step_kernel(const float* __restrict__ src0, const float* __restrict__ src1,
                      float* __restrict__ dst)
{
    const int t = blockIdx.y >> 4;        // blockIdx.y in [0,32): tensor*16+batch
    const int b = blockIdx.y & 15;
    const float* src = (t == 0 ? src0 : src1) + b * NIMG;
    float* out = dst + t * NTEN + b * NIMG;

    SKEL_SWEEP({
        *(float4*)(out + (size_t)orow * WW + gX) = o;
    })
}

__global__ __launch_bounds__(256)
void skel_final_kernel(const float* __restrict__ src0, const float* __restrict__ src1,
                       const float* __restrict__ other0, const float* __restrict__ other1)
{
    __shared__ float wprod[8], wsum[8];

    const int t = blockIdx.y >> 4;
    const int b = blockIdx.y & 15;
    const float* src   = (t == 0 ? src0   : src1)   + b * NIMG;
    const float* other = (t == 0 ? other0 : other1) + b * NIMG;

    float s_prod = 0.0f, s_sum = 0.0f;
    SKEL_SWEEP({
        const float4 ov = *(const float4*)(other + (size_t)orow * WW + gX);
        s_prod += o.x * ov.x + o.y * ov.y + o.z * ov.z + o.w * ov.w;
        s_sum  += o.x + o.y + o.z + o.w;
    })

    #pragma unroll
    for (int off = 16; off; off >>= 1) {
        s_prod += __shfl_down_sync(FULLM, s_prod, off);
        s_sum  += __shfl_down_sync(FULLM, s_sum,  off);
    }
    const int lane2 = threadIdx.x & 31;
    const int warp2 = threadIdx.x >> 5;
    if (lane2 == 0) { wprod[warp2] = s_prod; wsum[warp2] = s_sum; }
    __syncthreads();
    if (threadIdx.x == 0) {
        double p = 0.0, s = 0.0;
        #pragma unroll
        for (int i = 0; i < 8; i++) { p += (double)wprod[i]; s += (double)wsum[i]; }
        atomicAdd(&g_acc[t*2 + 0], p);
        atomicAdd(&g_acc[t*2 + 1], s);
    }
}

__global__ void finish_kernel(float* __restrict__ out)
{
    double iflat = (g_acc[0] + 1.0) / (g_acc[1] + 1.0);
    double tflat = (g_acc[2] + 1.0) / (g_acc[3] + 1.0);
    double loss  = 1.0 - 2.0 * iflat * tflat / (iflat + tflat);
    out[0] = (float)loss;
}

extern "C" void kernel_launch(void* const* d_in, const int* in_sizes, int n_in,
                              void* d_out, int out_size)
{
    const float* pred = (const float*)d_in[0];
    const float* gt   = (const float*)d_in[1];
    float* out = (float*)d_out;

    float *b0 = nullptr, *b1 = nullptr;
    cudaGetSymbolAddress((void**)&b0, g_buf0);
    cudaGetSymbolAddress((void**)&b1, g_buf1);

    dim3 grid(HH / RSWEEP, 2 * BATCH);   // (32, 32)
    const int threads = 256;             // 8 warps = 8 column strips

    zero_acc_kernel<<<1, 32>>>();

    // Iteration 0 reads the harness inputs.
    skel_step_kernel<<<grid, threads>>>(pred, gt, b0);

    // Iterations 1..18 ping-pong scratch.
    float* cur = b0;
    float* nxt = b1;
    for (int i = 1; i < 19; i++) {
        skel_step_kernel<<<grid, threads>>>(cur, cur + NTEN, nxt);
        float* tmp = cur; cur = nxt; nxt = tmp;
    }

    // Iteration 19 fused with the reductions.
    skel_final_kernel<<<grid, threads>>>(cur, cur + NTEN, gt, pred);

    finish_kernel<<<1, 1>>>(out);
}

// round 4
// speedup vs baseline: 4.0388x; 1.0469x over previous
#include <cuda_runtime.h>

#define HH 1024
#define WW 1024
#define BATCH 16
#define NIMG (HH*WW)
#define NTEN (BATCH*NIMG)
#define RSWEEP 32                  // output rows per warp sweep
#define FULLM 0xffffffffu

__device__ float g_buf0[2*NTEN];
__device__ float g_buf1[2*NTEN];
__device__ double g_acc[4];

__device__ __forceinline__ float PINF() { return __int_as_float(0x7f800000); }
__device__ __forceinline__ float NINF() { return __int_as_float(0xff800000); }
__device__ __forceinline__ float min3(float a, float b, float c) { return fminf(a, fminf(b, c)); }
__device__ __forceinline__ float max3(float a, float b, float c) { return fmaxf(a, fmaxf(b, c)); }

__global__ void zero_acc_kernel() {
    if (threadIdx.x < 4) g_acc[threadIdx.x] = 0.0;
}

// Warp-local skeleton sweep, 2 columns/thread (64-col strip per warp).
// Separable 3x3 min-pool then 3x3 max-pool; horizontal taps via shuffles,
// vertical taps via rolling registers. EMIT_BODY sees (orow, o0, o1):
// outputs for global row 'orow' at columns gX, gX+1.
#define SKEL_SWEEP(EMIT_BODY)                                                  \
    const int lane = threadIdx.x & 31;                                         \
    const int warp = threadIdx.x >> 5;                                         \
    const int c0   = blockIdx.y * 512 + warp * 64;                             \
    const int gX   = c0 + 2 * lane;                                            \
    const int r0   = blockIdx.x * RSWEEP;                                      \
    const bool leftok  = (c0 > 0);                                             \
    const bool rightok = (c0 + 64 < WW);                                       \
    float hA0 = PINF(), hA1 = PINF(), hB0 = PINF(), hB1 = PINF();              \
    float gA0 = NINF(), gA1 = NINF(), gB0 = NINF(), gB1 = NINF();              \
    float mC0 = 0.f, mC1 = 0.f;                                                \
    float hlA = PINF(), hlB = PINF(), hrA = PINF(), hrB = PINF();              \
    float xA0 = 0.f, xA1 = 0.f, xB0 = 0.f, xB1 = 0.f;                          \
    _Pragma("unroll 6")                                                        \
    for (int k = 0; k < RSWEEP + 4; k++) {                                     \
        const int rr = r0 - 2 + k;                                             \
        const bool rv = (rr >= 0) && (rr < HH);                                \
        float2 A;                                                              \
        if (rv) A = *(const float2*)(src + (size_t)rr * WW + gX);              \
        else    A = make_float2(PINF(), PINF());                               \
        float xl1 = PINF(), xl2 = PINF(), xr0 = PINF(), xr1 = PINF();          \
        if (lane == 0 && leftok && rv) {                                       \
            float2 tt = *(const float2*)(src + (size_t)rr * WW + c0 - 2);      \
            xl2 = tt.x; xl1 = tt.y;                                            \
        }                                                                      \
        if (lane == 31 && rightok && rv) {                                     \
            float2 tt = *(const float2*)(src + (size_t)rr * WW + c0 + 64);     \
            xr0 = tt.x; xr1 = tt.y;                                            \
        }                                                                      \
        float xm1 = __shfl_up_sync(FULLM, A.y, 1);                             \
        if (lane == 0) xm1 = xl1;                                              \
        float xp2 = __shfl_down_sync(FULLM, A.x, 1);                           \
        if (lane == 31) xp2 = xr0;                                             \
        float hC0 = min3(xm1, A.x, A.y);                                       \
        float hC1 = min3(A.x, A.y, xp2);                                       \
        float hlC = min3(xl2, xl1, A.x);                                       \
        float hrC = min3(A.y, xr0, xr1);                                       \
        float m0 = min3(hA0, hB0, hC0);                                        \
        float m1 = min3(hA1, hB1, hC1);                                        \
        float ml = min3(hlA, hlB, hlC);                                        \
        float mr = min3(hrA, hrB, hrC);                                        \
        const bool rvC = ((rr - 1) >= 0) && ((rr - 1) < HH);                   \
        float mM0 = rvC ? m0 : NINF();                                         \
        float mM1 = rvC ? m1 : NINF();                                         \
        float mlM = (leftok  && rvC) ? ml : NINF();                            \
        float mrM = (rightok && rvC) ? mr : NINF();                            \
        float mm1 = __shfl_up_sync(FULLM, mM1, 1);                             \
        if (lane == 0) mm1 = mlM;                                              \
        float mp2 = __shfl_down_sync(FULLM, mM0, 1);                           \
        if (lane == 31) mp2 = mrM;                                             \
        float gC0 = max3(mm1, mM0, mM1);                                       \
        float gC1 = max3(mM0, mM1, mp2);                                       \
        if (k >= 4) {                                                          \
            const int orow = rr - 2;                                           \
            float o0 = fmaxf(xA0 - fmaxf(max3(gA0, gB0, gC0) - mC0, 0.f), 0.f);\
            float o1 = fmaxf(xA1 - fmaxf(max3(gA1, gB1, gC1) - mC1, 0.f), 0.f);\
            EMIT_BODY                                                          \
        }                                                                      \
        hA0 = hB0; hA1 = hB1; hB0 = hC0; hB1 = hC1;                            \
        gA0 = gB0; gA1 = gB1; gB0 = gC0; gB1 = gC1;                            \
        mC0 = m0;  mC1 = m1;                                                   \
        hlA = hlB; hlB = hlC; hrA = hrB; hrB = hrC;                            \
        xA0 = xB0; xA1 = xB1; xB0 = A.x; xB1 = A.y;                            \
    }

__global__ __launch_bounds__(256, 5)
void skel_step_kernel(const float* __restrict__ src0, const float* __restrict__ src1,
                      float* __restrict__ dst)
{
    const int t = blockIdx.z >> 4;
    const int b = blockIdx.z & 15;
    const float* src = (t == 0 ? src0 : src1) + b * NIMG;
    float* out = dst + t * NTEN + b * NIMG;

    SKEL_SWEEP({
        *(float2*)(out + (size_t)orow * WW + gX) = make_float2(o0, o1);
    })
}

__global__ __launch_bounds__(256, 5)
void skel_final_kernel(const float* __restrict__ src0, const float* __restrict__ src1,
                       const float* __restrict__ other0, const float* __restrict__ other1)
{
    __shared__ float wprod[8], wsum[8];

    const int t = blockIdx.z >> 4;
    const int b = blockIdx.z & 15;
    const float* src   = (t == 0 ? src0   : src1)   + b * NIMG;
    const float* other = (t == 0 ? other0 : other1) + b * NIMG;

    float s_prod = 0.0f, s_sum = 0.0f;
    SKEL_SWEEP({
        const float2 ov = *(const float2*)(other + (size_t)orow * WW + gX);
        s_prod += o0 * ov.x + o1 * ov.y;
        s_sum  += o0 + o1;
    })

    #pragma unroll
    for (int off = 16; off; off >>= 1) {
        s_prod += __shfl_down_sync(FULLM, s_prod, off);
        s_sum  += __shfl_down_sync(FULLM, s_sum,  off);
    }
    const int lane2 = threadIdx.x & 31;
    const int warp2 = threadIdx.x >> 5;
    if (lane2 == 0) { wprod[warp2] = s_prod; wsum[warp2] = s_sum; }
    __syncthreads();
    if (threadIdx.x == 0) {
        double p = 0.0, s = 0.0;
        #pragma unroll
        for (int i = 0; i < 8; i++) { p += (double)wprod[i]; s += (double)wsum[i]; }
        atomicAdd(&g_acc[t*2 + 0], p);
        atomicAdd(&g_acc[t*2 + 1], s);
    }
}

__global__ void finish_kernel(float* __restrict__ out)
{
    double iflat = (g_acc[0] + 1.0) / (g_acc[1] + 1.0);
    double tflat = (g_acc[2] + 1.0) / (g_acc[3] + 1.0);
    double loss  = 1.0 - 2.0 * iflat * tflat / (iflat + tflat);
    out[0] = (float)loss;
}

extern "C" void kernel_launch(void* const* d_in, const int* in_sizes, int n_in,
                              void* d_out, int out_size)
{
    const float* pred = (const float*)d_in[0];
    const float* gt   = (const float*)d_in[1];
    float* out = (float*)d_out;

    float *b0 = nullptr, *b1 = nullptr;
    cudaGetSymbolAddress((void**)&b0, g_buf0);
    cudaGetSymbolAddress((void**)&b1, g_buf1);

    dim3 grid(HH / RSWEEP, 2, 2 * BATCH);   // (32, 2, 32) = 2048 blocks
    const int threads = 256;                // 8 warps x 64-col strips = 512 cols

    zero_acc_kernel<<<1, 32>>>();

    // Iteration 0 reads the harness inputs.
    skel_step_kernel<<<grid, threads>>>(pred, gt, b0);

    // Iterations 1..18 ping-pong scratch.
    float* cur = b0;
    float* nxt = b1;
    for (int i = 1; i < 19; i++) {
        skel_step_kernel<<<grid, threads>>>(cur, cur + NTEN, nxt);
        float* tmp = cur; cur = nxt; nxt = tmp;
    }

    // Iteration 19 fused with the reductions.
    skel_final_kernel<<<grid, threads>>>(cur, cur + NTEN, gt, pred);

    finish_kernel<<<1, 1>>>(out);
}